// round 6
// baseline (speedup 1.0000x reference)
#include <cuda_runtime.h>
#include <cstddef>
#include <cstdint>

#define T_LEN 256
#define BATCH 32
#define VOCAB 32000
#define EMB 512
#define HID 1024
#define G4 4096
#define MROWS 8192  // T*B

// ---------------- scratch (no cudaMalloc allowed) ----------------
__device__ float g_X0[MROWS * EMB];
__device__ float g_G [MROWS * G4];
__device__ float g_Ha[MROWS * HID];
__device__ float g_Hb[MROWS * HID];
__device__ float g_C [BATCH * HID];

// ---------------- helpers ----------------
__device__ __forceinline__ unsigned f2tf32(float x) {
    unsigned r;
    asm("cvt.rna.tf32.f32 %0, %1;" : "=r"(r) : "f"(x));
    return r;
}

__device__ __forceinline__ void mma_tf32(float* d, const unsigned* a, const unsigned* b) {
    asm volatile(
        "mma.sync.aligned.m16n8k8.row.col.f32.tf32.tf32.f32 "
        "{%0,%1,%2,%3}, {%4,%5,%6,%7}, {%8,%9}, {%0,%1,%2,%3};\n"
        : "+f"(d[0]), "+f"(d[1]), "+f"(d[2]), "+f"(d[3])
        : "r"(a[0]), "r"(a[1]), "r"(a[2]), "r"(a[3]), "r"(b[0]), "r"(b[1]));
}

__device__ __forceinline__ void cp16(void* smem_dst, const void* gsrc) {
    unsigned d = (unsigned)__cvta_generic_to_shared(smem_dst);
    asm volatile("cp.async.cg.shared.global [%0], [%1], 16;\n" :: "r"(d), "l"(gsrc));
}
__device__ __forceinline__ void cp_commit() { asm volatile("cp.async.commit_group;\n" ::); }
__device__ __forceinline__ void cp_wait0()  { asm volatile("cp.async.wait_group 0;\n" ::: "memory"); }

__device__ __forceinline__ float sigmf(float x) { return 1.f / (1.f + expf(-x)); }

// ---------------- embedding gather (int32/int64 token auto-detect) ----------------
__global__ void embed_kernel(const void* __restrict__ data, const float* __restrict__ emb,
                             float* __restrict__ X) {
    const int r = blockIdx.x;
    const unsigned* d32 = (const unsigned*)data;
    // If tokens are int64 (little-endian, values < 32000), every odd 32-bit word
    // of the first 16 pairs is 0. For int32 tokens those words are random nonzero
    // tokens (P(all 16 == 0) ~ 1e-72). Deterministic, identical across blocks.
    unsigned hi = 0;
#pragma unroll
    for (int k = 0; k < 16; ++k) hi |= d32[2 * k + 1];
    long long idx;
    if (hi == 0) idx = ((const long long*)data)[r];
    else         idx = (long long)((const int*)data)[r];
    const float4* s = (const float4*)(emb + (size_t)idx * EMB);
    float4* dst = (float4*)(X + (size_t)r * EMB);
    dst[threadIdx.x] = s[threadIdx.x];  // 128 threads x float4 = 512 floats
}

// ---------------- tf32 GEMM: C[M,N] = A[M,K] @ B[K,N] + bias[N] ----------------
// M = 8192 fixed; K in {512,1024}; N in {4096,32000}. All divisible by tiles.
#define GBM 128
#define GBN 128
#define GBK 16
#define LDA 20
#define LDB 136

__global__ void __launch_bounds__(256) gemm_tf32_kernel(
        const float* __restrict__ A, const float* __restrict__ B,
        const float* __restrict__ bias, float* __restrict__ C, int K, int N) {
    __shared__ float As[2][GBM * LDA];
    __shared__ float Bs[2][GBK * LDB];
    const int tid = threadIdx.x;
    const int lane = tid & 31, w = tid >> 5;
    const int wm = w >> 1, wn = w & 1;      // 4x2 warp grid, warp tile 32x64
    const int gi = lane >> 2, tg = lane & 3;
    const int bm = blockIdx.y, bn = blockIdx.x;

    const float* Ag = A + (size_t)bm * GBM * K;
    const float* Bg = B + (size_t)bn * GBN;

    const int ar  = tid >> 1;            // 0..127
    const int ac0 = (tid & 1) * 8;       // two float4 at ac0, ac0+4
    const int br  = tid >> 4;            // 0..15
    const int bc  = (tid & 15) * 4;      // two float4 at bc, bc+64

    float acc[2][8][4];
#pragma unroll
    for (int m = 0; m < 2; ++m)
#pragma unroll
        for (int n = 0; n < 8; ++n)
#pragma unroll
            for (int q = 0; q < 4; ++q) acc[m][n][q] = 0.f;

    auto stage = [&](int s, int kt) {
        const float* asrc = Ag + (size_t)ar * K + kt * GBK + ac0;
        float* adst = &As[s][ar * LDA + ac0];
        cp16(adst, asrc); cp16(adst + 4, asrc + 4);
        const float* bsrc = Bg + (size_t)(kt * GBK + br) * N + bc;
        float* bdst = &Bs[s][br * LDB + bc];
        cp16(bdst, bsrc); cp16(bdst + 64, bsrc + 64);
        cp_commit();
    };

    auto compute = [&](int s) {
#pragma unroll
        for (int ks = 0; ks < 2; ++ks) {
            unsigned af[2][4], bf[8][2];
#pragma unroll
            for (int m = 0; m < 2; ++m) {
                int rb = wm * 32 + m * 16;
                af[m][0] = f2tf32(As[s][(rb + gi) * LDA + ks * 8 + tg]);
                af[m][1] = f2tf32(As[s][(rb + gi + 8) * LDA + ks * 8 + tg]);
                af[m][2] = f2tf32(As[s][(rb + gi) * LDA + ks * 8 + tg + 4]);
                af[m][3] = f2tf32(As[s][(rb + gi + 8) * LDA + ks * 8 + tg + 4]);
            }
#pragma unroll
            for (int n = 0; n < 8; ++n) {
                int cb = wn * 64 + n * 8 + gi;
                bf[n][0] = f2tf32(Bs[s][(ks * 8 + tg) * LDB + cb]);
                bf[n][1] = f2tf32(Bs[s][(ks * 8 + tg + 4) * LDB + cb]);
            }
#pragma unroll
            for (int m = 0; m < 2; ++m)
#pragma unroll
                for (int n = 0; n < 8; ++n)
                    mma_tf32(acc[m][n], af[m], bf[n]);
        }
    };

    const int KT = K >> 4;
    stage(0, 0);
    for (int kt = 0; kt < KT; ++kt) {
        cp_wait0();
        __syncthreads();
        if (kt + 1 < KT) stage((kt + 1) & 1, kt + 1);
        compute(kt & 1);
    }

    // epilogue: add bias, write fp32
#pragma unroll
    for (int m = 0; m < 2; ++m) {
        int row = bm * GBM + wm * 32 + m * 16 + gi;
#pragma unroll
        for (int n = 0; n < 8; ++n) {
            int col = bn * GBN + wn * 64 + n * 8 + 2 * tg;
            float bi0 = bias[col], bi1 = bias[col + 1];
            float2 v0 = make_float2(acc[m][n][0] + bi0, acc[m][n][1] + bi1);
            float2 v1 = make_float2(acc[m][n][2] + bi0, acc[m][n][3] + bi1);
            *(float2*)(C + (size_t)row * N + col) = v0;
            *(float2*)(C + (size_t)(row + 8) * N + col) = v1;
        }
    }
}

// ---------------- one LSTM timestep (no inter-CTA sync anywhere) ----------------
// Grid: 32 blocks x 256 threads. Block b owns hidden units [b*32, b*32+32),
// i.e. gate columns q*1024 + b*32 + u for q in 0..3 (128 Wh columns).
// gates = G[t] + h_{t-1} @ Wh ; elementwise LSTM ; write h_t, c_t.
// Wh streams from L2 (resident: 16MB < 126MB) in K-chunks of 64 via cp.async.
#define WS_LD 136
#define HS_LD 68
#define GS_LD 132
#define WS_SZ (64 * WS_LD)
#define HS_SZ (32 * HS_LD)
#define STEP_SMEM ((2 * WS_SZ + 2 * HS_SZ + 32 * GS_LD) * 4)

__global__ void __launch_bounds__(256) step_kernel(
        const float* __restrict__ G, const float* __restrict__ W, int Din,
        float* __restrict__ H, float* __restrict__ C, int t) {
    extern __shared__ float sm[];
    float* Ws = sm;                          // 2 x [64][136]
    float* Hs = sm + 2 * WS_SZ;              // 2 x [32][68]
    float* Gs = sm + 2 * WS_SZ + 2 * HS_SZ;  // [32][132]

    const int tid = threadIdx.x, b = blockIdx.x;
    const int lane = tid & 31, w = tid >> 5;
    const int mt = w >> 2, nt = w & 3;       // 2 m-tiles x 4 n-tiles
    const int gi = lane >> 2, tg = lane & 3;

    if (t > 0) {
        // staging maps
        const int wrow = tid >> 2;           // 0..63  (k within chunk)
        const int q    = tid & 3;            // gate group; loads 32 contiguous floats
        const int hrow = tid >> 3;           // 0..31  (batch)
        const int hc   = (tid & 7) * 8;      // 8 floats
        const float* hp = H + (size_t)(t - 1) * BATCH * HID;

        auto stageS = [&](int s, int kc) {
            const float* wr = W + (size_t)(Din + kc * 64 + wrow) * G4 + q * HID + b * 32;
            float* wd = Ws + s * WS_SZ + wrow * WS_LD + q * 32;
#pragma unroll
            for (int f = 0; f < 8; ++f) cp16(wd + f * 4, wr + f * 4);
            const float* hr = hp + (size_t)hrow * HID + kc * 64 + hc;
            float* hd = Hs + s * HS_SZ + hrow * HS_LD + hc;
            cp16(hd, hr); cp16(hd + 4, hr + 4);
            cp_commit();
        };

        float acc[4][4];
#pragma unroll
        for (int j = 0; j < 4; ++j)
#pragma unroll
            for (int v = 0; v < 4; ++v) acc[j][v] = 0.f;

        stageS(0, 0);
        for (int kc = 0; kc < 16; ++kc) {
            cp_wait0();
            __syncthreads();
            if (kc < 15) stageS((kc + 1) & 1, kc + 1);
            const float* hb = Hs + (kc & 1) * HS_SZ;
            const float* wb = Ws + (kc & 1) * WS_SZ;
#pragma unroll
            for (int kk = 0; kk < 8; ++kk) {
                const int k8 = kk * 8;
                unsigned a[4], bf[2];
                a[0] = f2tf32(hb[(mt * 16 + gi) * HS_LD + k8 + tg]);
                a[1] = f2tf32(hb[(mt * 16 + gi + 8) * HS_LD + k8 + tg]);
                a[2] = f2tf32(hb[(mt * 16 + gi) * HS_LD + k8 + tg + 4]);
                a[3] = f2tf32(hb[(mt * 16 + gi + 8) * HS_LD + k8 + tg + 4]);
#pragma unroll
                for (int j = 0; j < 4; ++j) {
                    bf[0] = f2tf32(wb[(k8 + tg) * WS_LD + nt * 32 + j * 8 + gi]);
                    bf[1] = f2tf32(wb[(k8 + tg + 4) * WS_LD + nt * 32 + j * 8 + gi]);
                    mma_tf32(acc[j], a, bf);
                }
            }
        }
        // scatter recurrent gate partials for the elementwise phase
#pragma unroll
        for (int j = 0; j < 4; ++j) {
            int col = nt * 32 + j * 8 + 2 * tg;
            int r0 = (mt * 16 + gi) * GS_LD + col;
            int r1 = (mt * 16 + gi + 8) * GS_LD + col;
            Gs[r0] = acc[j][0]; Gs[r0 + 1] = acc[j][1];
            Gs[r1] = acc[j][2]; Gs[r1 + 1] = acc[j][3];
        }
    }
    __syncthreads();

    // elementwise LSTM: thread -> (batch eb, 4 consecutive units)
    {
        const int eb = tid >> 3;
        const int u0 = (tid & 7) * 4;
        const size_t go = ((size_t)t * BATCH + eb) * G4 + b * 32 + u0;
        float4 gi4 = *(const float4*)(G + go);
        float4 gg4 = *(const float4*)(G + go + 1024);
        float4 gf4 = *(const float4*)(G + go + 2048);
        float4 go4 = *(const float4*)(G + go + 3072);
        float4 cp4 = make_float4(0.f, 0.f, 0.f, 0.f);
        float s_i[4] = {0, 0, 0, 0}, s_g[4] = {0, 0, 0, 0};
        float s_f[4] = {0, 0, 0, 0}, s_o[4] = {0, 0, 0, 0};
        if (t > 0) {
            cp4 = *(const float4*)(C + eb * HID + b * 32 + u0);
#pragma unroll
            for (int r = 0; r < 4; ++r) {
                s_i[r] = Gs[eb * GS_LD + u0 + r];
                s_g[r] = Gs[eb * GS_LD + 32 + u0 + r];
                s_f[r] = Gs[eb * GS_LD + 64 + u0 + r];
                s_o[r] = Gs[eb * GS_LD + 96 + u0 + r];
            }
        }
        float ivv[4] = {gi4.x, gi4.y, gi4.z, gi4.w};
        float gvv[4] = {gg4.x, gg4.y, gg4.z, gg4.w};
        float fvv[4] = {gf4.x, gf4.y, gf4.z, gf4.w};
        float ovv[4] = {go4.x, go4.y, go4.z, go4.w};
        float cpv[4] = {cp4.x, cp4.y, cp4.z, cp4.w};
        float cn[4], hn[4];
#pragma unroll
        for (int r = 0; r < 4; ++r) {
            float iv = s_i[r] + ivv[r];
            float gv = s_g[r] + gvv[r];
            float fv = s_f[r] + fvv[r];
            float ov = s_o[r] + ovv[r];
            cn[r] = sigmf(fv + 1.f) * cpv[r] + sigmf(iv) * tanhf(gv);
            hn[r] = sigmf(ov) * tanhf(cn[r]);
        }
        *(float4*)(C + eb * HID + b * 32 + u0) = make_float4(cn[0], cn[1], cn[2], cn[3]);
        *(float4*)(H + ((size_t)t * BATCH + eb) * HID + b * 32 + u0) =
            make_float4(hn[0], hn[1], hn[2], hn[3]);
    }
}

// ---------------- launch ----------------
extern "C" void kernel_launch(void* const* d_in, const int* in_sizes, int n_in,
                              void* d_out, int out_size) {
    (void)in_sizes; (void)n_in; (void)out_size;
    const void*  data = d_in[0];
    // d_in[1] = is_training (eval mode; unused)
    const float* emb  = (const float*)d_in[2];
    const float* W0   = (const float*)d_in[3];
    const float* b0   = (const float*)d_in[4];
    const float* W1   = (const float*)d_in[5];
    const float* b1   = (const float*)d_in[6];
    const float* W2   = (const float*)d_in[7];
    const float* b2   = (const float*)d_in[8];
    const float* Wd   = (const float*)d_in[9];
    const float* bd   = (const float*)d_in[10];
    float* out = (float*)d_out;

    void *pX0, *pG, *pHa, *pHb, *pC;
    cudaGetSymbolAddress(&pX0, g_X0);
    cudaGetSymbolAddress(&pG,  g_G);
    cudaGetSymbolAddress(&pHa, g_Ha);
    cudaGetSymbolAddress(&pHb, g_Hb);
    cudaGetSymbolAddress(&pC,  g_C);
    float* X0 = (float*)pX0;
    float* G  = (float*)pG;
    float* Ha = (float*)pHa;
    float* Hb = (float*)pHb;
    float* C  = (float*)pC;

    cudaFuncSetAttribute(step_kernel, cudaFuncAttributeMaxDynamicSharedMemorySize, STEP_SMEM);

    embed_kernel<<<MROWS, 128>>>(data, emb, X0);

    // layer 0
    gemm_tf32_kernel<<<dim3(G4 / GBN, MROWS / GBM), 256>>>(X0, W0, b0, G, EMB, G4);
    for (int t = 0; t < T_LEN; ++t)
        step_kernel<<<32, 256, STEP_SMEM>>>(G, W0, EMB, Ha, C, t);
    // layer 1
    gemm_tf32_kernel<<<dim3(G4 / GBN, MROWS / GBM), 256>>>(Ha, W1, b1, G, HID, G4);
    for (int t = 0; t < T_LEN; ++t)
        step_kernel<<<32, 256, STEP_SMEM>>>(G, W1, HID, Hb, C, t);
    // layer 2
    gemm_tf32_kernel<<<dim3(G4 / GBN, MROWS / GBM), 256>>>(Hb, W2, b2, G, HID, G4);
    for (int t = 0; t < T_LEN; ++t)
        step_kernel<<<32, 256, STEP_SMEM>>>(G, W2, HID, Ha, C, t);
    // decoder
    gemm_tf32_kernel<<<dim3(VOCAB / GBN, MROWS / GBM), 256>>>(Ha, Wd, bd, out, HID, VOCAB);
}

// round 7
// speedup vs baseline: 1.7947x; 1.7947x over previous
#include <cuda_runtime.h>
#include <cstddef>
#include <cstdint>

#define T_LEN 256
#define BATCH 32
#define VOCAB 32000
#define EMB 512
#define HID 1024
#define G4 4096
#define MROWS 8192  // T*B

// ---------------- scratch (no cudaMalloc allowed) ----------------
__device__ float g_X0[MROWS * EMB];
__device__ float g_G [MROWS * G4];
__device__ float g_Ha[MROWS * HID];
__device__ float g_Hb[MROWS * HID];
__device__ float g_C [BATCH * HID];

// ---------------- helpers ----------------
__device__ __forceinline__ unsigned f2tf32(float x) {
    unsigned r;
    asm("cvt.rna.tf32.f32 %0, %1;" : "=r"(r) : "f"(x));
    return r;
}

__device__ __forceinline__ void mma_tf32(float* d, const unsigned* a, const unsigned* b) {
    asm volatile(
        "mma.sync.aligned.m16n8k8.row.col.f32.tf32.tf32.f32 "
        "{%0,%1,%2,%3}, {%4,%5,%6,%7}, {%8,%9}, {%0,%1,%2,%3};\n"
        : "+f"(d[0]), "+f"(d[1]), "+f"(d[2]), "+f"(d[3])
        : "r"(a[0]), "r"(a[1]), "r"(a[2]), "r"(a[3]), "r"(b[0]), "r"(b[1]));
}

__device__ __forceinline__ void cp16(void* smem_dst, const void* gsrc) {
    unsigned d = (unsigned)__cvta_generic_to_shared(smem_dst);
    asm volatile("cp.async.cg.shared.global [%0], [%1], 16;\n" :: "r"(d), "l"(gsrc));
}
__device__ __forceinline__ void cp_commit() { asm volatile("cp.async.commit_group;\n" ::); }
__device__ __forceinline__ void cp_wait0()  { asm volatile("cp.async.wait_group 0;\n" ::: "memory"); }
__device__ __forceinline__ void cp_wait1()  { asm volatile("cp.async.wait_group 1;\n" ::: "memory"); }
__device__ __forceinline__ void cp_wait2()  { asm volatile("cp.async.wait_group 2;\n" ::: "memory"); }

__device__ __forceinline__ float sigmf(float x) { return 1.f / (1.f + expf(-x)); }

// ---------------- embedding gather (int32/int64 token auto-detect) ----------------
__global__ void embed_kernel(const void* __restrict__ data, const float* __restrict__ emb,
                             float* __restrict__ X) {
    const int r = blockIdx.x;
    const unsigned* d32 = (const unsigned*)data;
    unsigned hi = 0;
#pragma unroll
    for (int k = 0; k < 16; ++k) hi |= d32[2 * k + 1];
    long long idx;
    if (hi == 0) idx = ((const long long*)data)[r];
    else         idx = (long long)((const int*)data)[r];
    const float4* s = (const float4*)(emb + (size_t)idx * EMB);
    float4* dst = (float4*)(X + (size_t)r * EMB);
    dst[threadIdx.x] = s[threadIdx.x];  // 128 threads x float4 = 512 floats
}

// ---------------- tf32 GEMM: C[M,N] = A[M,K] @ B[K,N] + bias[N] ----------------
#define GBM 128
#define GBN 128
#define GBK 16
#define LDA 20
#define LDB 136

__global__ void __launch_bounds__(256) gemm_tf32_kernel(
        const float* __restrict__ A, const float* __restrict__ B,
        const float* __restrict__ bias, float* __restrict__ C, int K, int N) {
    __shared__ float As[2][GBM * LDA];
    __shared__ float Bs[2][GBK * LDB];
    const int tid = threadIdx.x;
    const int lane = tid & 31, w = tid >> 5;
    const int wm = w >> 1, wn = w & 1;      // 4x2 warp grid, warp tile 32x64
    const int gi = lane >> 2, tg = lane & 3;
    const int bm = blockIdx.y, bn = blockIdx.x;

    const float* Ag = A + (size_t)bm * GBM * K;
    const float* Bg = B + (size_t)bn * GBN;

    const int ar  = tid >> 1;
    const int ac0 = (tid & 1) * 8;
    const int br  = tid >> 4;
    const int bc  = (tid & 15) * 4;

    float acc[2][8][4];
#pragma unroll
    for (int m = 0; m < 2; ++m)
#pragma unroll
        for (int n = 0; n < 8; ++n)
#pragma unroll
            for (int q = 0; q < 4; ++q) acc[m][n][q] = 0.f;

    auto stage = [&](int s, int kt) {
        const float* asrc = Ag + (size_t)ar * K + kt * GBK + ac0;
        float* adst = &As[s][ar * LDA + ac0];
        cp16(adst, asrc); cp16(adst + 4, asrc + 4);
        const float* bsrc = Bg + (size_t)(kt * GBK + br) * N + bc;
        float* bdst = &Bs[s][br * LDB + bc];
        cp16(bdst, bsrc); cp16(bdst + 64, bsrc + 64);
        cp_commit();
    };

    auto compute = [&](int s) {
#pragma unroll
        for (int ks = 0; ks < 2; ++ks) {
            unsigned af[2][4], bf[8][2];
#pragma unroll
            for (int m = 0; m < 2; ++m) {
                int rb = wm * 32 + m * 16;
                af[m][0] = f2tf32(As[s][(rb + gi) * LDA + ks * 8 + tg]);
                af[m][1] = f2tf32(As[s][(rb + gi + 8) * LDA + ks * 8 + tg]);
                af[m][2] = f2tf32(As[s][(rb + gi) * LDA + ks * 8 + tg + 4]);
                af[m][3] = f2tf32(As[s][(rb + gi + 8) * LDA + ks * 8 + tg + 4]);
            }
#pragma unroll
            for (int n = 0; n < 8; ++n) {
                int cb = wn * 64 + n * 8 + gi;
                bf[n][0] = f2tf32(Bs[s][(ks * 8 + tg) * LDB + cb]);
                bf[n][1] = f2tf32(Bs[s][(ks * 8 + tg + 4) * LDB + cb]);
            }
#pragma unroll
            for (int m = 0; m < 2; ++m)
#pragma unroll
                for (int n = 0; n < 8; ++n)
                    mma_tf32(acc[m][n], af[m], bf[n]);
        }
    };

    const int KT = K >> 4;
    stage(0, 0);
    for (int kt = 0; kt < KT; ++kt) {
        cp_wait0();
        __syncthreads();
        if (kt + 1 < KT) stage((kt + 1) & 1, kt + 1);
        compute(kt & 1);
    }

#pragma unroll
    for (int m = 0; m < 2; ++m) {
        int row = bm * GBM + wm * 32 + m * 16 + gi;
#pragma unroll
        for (int n = 0; n < 8; ++n) {
            int col = bn * GBN + wn * 64 + n * 8 + 2 * tg;
            float bi0 = bias[col], bi1 = bias[col + 1];
            float2 v0 = make_float2(acc[m][n][0] + bi0, acc[m][n][1] + bi1);
            float2 v1 = make_float2(acc[m][n][2] + bi0, acc[m][n][3] + bi1);
            *(float2*)(C + (size_t)row * N + col) = v0;
            *(float2*)(C + (size_t)(row + 8) * N + col) = v1;
        }
    }
}

// ---------------- one LSTM timestep v2 (wide + deep pipeline) ----------------
// Grid: 128 blocks x 256 threads. Block b owns hidden units [b*8, b*8+8),
// i.e. gate columns q*1024 + b*8 + j (32 cols). K = 1024 in 8 chunks of 128,
// 4-stage cp.async pipeline with 3 chunks in flight.
#define SK_STAGES 4
#define SKW_LD 40                       // bank-conflict-free: 40 % 32 = 8
#define SKH_LD 132                      // 132 % 32 = 4
#define SKG_LD 36
#define SKW_SZ (128 * SKW_LD)
#define SKH_SZ (32 * SKH_LD)
#define SK_STAGE_SZ (SKW_SZ + SKH_SZ)
#define STEP_SMEM ((SK_STAGES * SK_STAGE_SZ + 32 * SKG_LD) * 4)

__global__ void __launch_bounds__(256) step_kernel(
        const float* __restrict__ G, const float* __restrict__ W, int Din,
        float* __restrict__ H, float* __restrict__ C, int t) {
    extern __shared__ float sm[];
    float* Gs = sm + SK_STAGES * SK_STAGE_SZ;   // [32][36] recurrent gate partials

    const int tid = threadIdx.x, b = blockIdx.x;
    const int lane = tid & 31, w = tid >> 5;
    const int mt = w >> 2, nt = w & 3;          // 2 m-tiles x 4 n-tiles (8 warps)
    const int gi = lane >> 2, tg = lane & 3;

    if (t > 0) {
        const float* hp = H + (size_t)(t - 1) * BATCH * HID;
        // staging maps
        const int wr_ = tid >> 1;               // 0..127 : k-row within chunk
        const int qh  = (tid & 1) * 2;          // gate-group pair {0,1} or {2,3}
        const int hm  = tid >> 3;               // 0..31  : batch row
        const int hc  = (tid & 7) * 16;         // 16-float segment

        auto stageS = [&](int s, int kc) {
            float* Wst = sm + s * SK_STAGE_SZ;
            float* Hst = Wst + SKW_SZ;
            const float* wsrc = W + (size_t)(Din + kc * 128 + wr_) * G4 + b * 8;
            float* wdst = Wst + wr_ * SKW_LD;
            cp16(wdst + qh * 8,           wsrc + qh * 1024);
            cp16(wdst + qh * 8 + 4,       wsrc + qh * 1024 + 4);
            cp16(wdst + (qh + 1) * 8,     wsrc + (qh + 1) * 1024);
            cp16(wdst + (qh + 1) * 8 + 4, wsrc + (qh + 1) * 1024 + 4);
            const float* hsrc = hp + (size_t)hm * HID + kc * 128 + hc;
            float* hdst = Hst + hm * SKH_LD + hc;
            cp16(hdst, hsrc);         cp16(hdst + 4, hsrc + 4);
            cp16(hdst + 8, hsrc + 8); cp16(hdst + 12, hsrc + 12);
            cp_commit();
        };

        float acc[4] = {0.f, 0.f, 0.f, 0.f};

        stageS(0, 0); stageS(1, 1); stageS(2, 2);
        for (int kc = 0; kc < 8; ++kc) {
            if (kc <= 5)      cp_wait2();
            else if (kc == 6) cp_wait1();
            else              cp_wait0();
            __syncthreads();
            if (kc + 3 < 8) stageS((kc + 3) & 3, kc + 3);
            const float* Wst = sm + (kc & 3) * SK_STAGE_SZ;
            const float* Hst = Wst + SKW_SZ;
#pragma unroll
            for (int kk = 0; kk < 16; ++kk) {
                const int k8 = kk * 8;
                unsigned a[4], bf[2];
                a[0] = f2tf32(Hst[(mt * 16 + gi) * SKH_LD + k8 + tg]);
                a[1] = f2tf32(Hst[(mt * 16 + gi + 8) * SKH_LD + k8 + tg]);
                a[2] = f2tf32(Hst[(mt * 16 + gi) * SKH_LD + k8 + tg + 4]);
                a[3] = f2tf32(Hst[(mt * 16 + gi + 8) * SKH_LD + k8 + tg + 4]);
                bf[0] = f2tf32(Wst[(k8 + tg) * SKW_LD + nt * 8 + gi]);
                bf[1] = f2tf32(Wst[(k8 + tg + 4) * SKW_LD + nt * 8 + gi]);
                mma_tf32(acc, a, bf);
            }
            __syncthreads();
        }
        // scatter recurrent gate partials (warp tile m16n8 at (mt, nt))
        {
            int col = nt * 8 + 2 * tg;
            int r0 = (mt * 16 + gi) * SKG_LD + col;
            int r1 = (mt * 16 + gi + 8) * SKG_LD + col;
            Gs[r0] = acc[0]; Gs[r0 + 1] = acc[1];
            Gs[r1] = acc[2]; Gs[r1 + 1] = acc[3];
        }
    }
    __syncthreads();

    // elementwise LSTM: one (batch, unit) per thread
    {
        const int eb = tid >> 3;                 // 0..31
        const int j  = tid & 7;                  // 0..7
        const size_t go = ((size_t)t * BATCH + eb) * G4 + b * 8 + j;
        float iv = G[go];
        float gv = G[go + 1024];
        float fv = G[go + 2048];
        float ov = G[go + 3072];
        float cprev = 0.f;
        if (t > 0) {
            iv += Gs[eb * SKG_LD + j];
            gv += Gs[eb * SKG_LD + 8 + j];
            fv += Gs[eb * SKG_LD + 16 + j];
            ov += Gs[eb * SKG_LD + 24 + j];
            cprev = C[eb * HID + b * 8 + j];
        }
        float cn = sigmf(fv + 1.f) * cprev + sigmf(iv) * tanhf(gv);
        float hn = sigmf(ov) * tanhf(cn);
        C[eb * HID + b * 8 + j] = cn;
        H[((size_t)t * BATCH + eb) * HID + b * 8 + j] = hn;
    }
}

// ---------------- launch ----------------
extern "C" void kernel_launch(void* const* d_in, const int* in_sizes, int n_in,
                              void* d_out, int out_size) {
    (void)in_sizes; (void)n_in; (void)out_size;
    const void*  data = d_in[0];
    // d_in[1] = is_training (eval mode; unused)
    const float* emb  = (const float*)d_in[2];
    const float* W0   = (const float*)d_in[3];
    const float* b0   = (const float*)d_in[4];
    const float* W1   = (const float*)d_in[5];
    const float* b1   = (const float*)d_in[6];
    const float* W2   = (const float*)d_in[7];
    const float* b2   = (const float*)d_in[8];
    const float* Wd   = (const float*)d_in[9];
    const float* bd   = (const float*)d_in[10];
    float* out = (float*)d_out;

    void *pX0, *pG, *pHa, *pHb, *pC;
    cudaGetSymbolAddress(&pX0, g_X0);
    cudaGetSymbolAddress(&pG,  g_G);
    cudaGetSymbolAddress(&pHa, g_Ha);
    cudaGetSymbolAddress(&pHb, g_Hb);
    cudaGetSymbolAddress(&pC,  g_C);
    float* X0 = (float*)pX0;
    float* G  = (float*)pG;
    float* Ha = (float*)pHa;
    float* Hb = (float*)pHb;
    float* C  = (float*)pC;

    cudaFuncSetAttribute(step_kernel, cudaFuncAttributeMaxDynamicSharedMemorySize, STEP_SMEM);

    embed_kernel<<<MROWS, 128>>>(data, emb, X0);

    // layer 0
    gemm_tf32_kernel<<<dim3(G4 / GBN, MROWS / GBM), 256>>>(X0, W0, b0, G, EMB, G4);
    for (int t = 0; t < T_LEN; ++t)
        step_kernel<<<128, 256, STEP_SMEM>>>(G, W0, EMB, Ha, C, t);
    // layer 1
    gemm_tf32_kernel<<<dim3(G4 / GBN, MROWS / GBM), 256>>>(Ha, W1, b1, G, HID, G4);
    for (int t = 0; t < T_LEN; ++t)
        step_kernel<<<128, 256, STEP_SMEM>>>(G, W1, HID, Hb, C, t);
    // layer 2
    gemm_tf32_kernel<<<dim3(G4 / GBN, MROWS / GBM), 256>>>(Hb, W2, b2, G, HID, G4);
    for (int t = 0; t < T_LEN; ++t)
        step_kernel<<<128, 256, STEP_SMEM>>>(G, W2, HID, Ha, C, t);
    // decoder
    gemm_tf32_kernel<<<dim3(VOCAB / GBN, MROWS / GBM), 256>>>(Ha, Wd, bd, out, HID, VOCAB);
}

// round 8
// speedup vs baseline: 2.0782x; 1.1580x over previous
#include <cuda_runtime.h>
#include <cstddef>
#include <cstdint>

#define T_LEN 256
#define BATCH 32
#define VOCAB 32000
#define EMB 512
#define HID 1024
#define G4 4096
#define MROWS 8192  // T*B

// ---------------- scratch (no cudaMalloc allowed) ----------------
__device__ float g_X0[MROWS * EMB];
__device__ float g_G [MROWS * G4];
__device__ float g_Ha[MROWS * HID];
__device__ float g_Hb[MROWS * HID];
__device__ float g_C [BATCH * HID];
__device__ float g_Wr[3 * HID * G4];   // pre-tf32-rounded recurrent weights, 3 layers

// ---------------- helpers ----------------
__device__ __forceinline__ unsigned f2tf32(float x) {
    unsigned r;
    asm("cvt.rna.tf32.f32 %0, %1;" : "=r"(r) : "f"(x));
    return r;
}

__device__ __forceinline__ void mma_tf32(float* d, const unsigned* a, const unsigned* b) {
    asm volatile(
        "mma.sync.aligned.m16n8k8.row.col.f32.tf32.tf32.f32 "
        "{%0,%1,%2,%3}, {%4,%5,%6,%7}, {%8,%9}, {%0,%1,%2,%3};\n"
        : "+f"(d[0]), "+f"(d[1]), "+f"(d[2]), "+f"(d[3])
        : "r"(a[0]), "r"(a[1]), "r"(a[2]), "r"(a[3]), "r"(b[0]), "r"(b[1]));
}

__device__ __forceinline__ void cp16(void* smem_dst, const void* gsrc) {
    unsigned d = (unsigned)__cvta_generic_to_shared(smem_dst);
    asm volatile("cp.async.cg.shared.global [%0], [%1], 16;\n" :: "r"(d), "l"(gsrc));
}
__device__ __forceinline__ void cp_commit() { asm volatile("cp.async.commit_group;\n" ::); }
__device__ __forceinline__ void cp_wait0()  { asm volatile("cp.async.wait_group 0;\n" ::: "memory"); }
__device__ __forceinline__ void cp_wait1()  { asm volatile("cp.async.wait_group 1;\n" ::: "memory"); }
__device__ __forceinline__ void cp_wait2()  { asm volatile("cp.async.wait_group 2;\n" ::: "memory"); }

__device__ __forceinline__ float sigmf(float x) { return 1.f / (1.f + expf(-x)); }

// ---------------- embedding gather (int32/int64 token auto-detect) ----------------
__global__ void embed_kernel(const void* __restrict__ data, const float* __restrict__ emb,
                             float* __restrict__ X) {
    const int r = blockIdx.x;
    const unsigned* d32 = (const unsigned*)data;
    unsigned hi = 0;
#pragma unroll
    for (int k = 0; k < 16; ++k) hi |= d32[2 * k + 1];
    long long idx;
    if (hi == 0) idx = ((const long long*)data)[r];
    else         idx = (long long)((const int*)data)[r];
    const float4* s = (const float4*)(emb + (size_t)idx * EMB);
    float4* dst = (float4*)(X + (size_t)r * EMB);
    dst[threadIdx.x] = s[threadIdx.x];
}

// ---------------- pre-round recurrent weights to tf32 ----------------
// One block per k-row (1024 rows); copies W[Din + row][0..4095] tf32-rounded.
__global__ void preround_kernel(const float* __restrict__ Wsrc, float* __restrict__ Wdst) {
    const int row = blockIdx.x;
    const float4* s = (const float4*)(Wsrc + (size_t)row * G4);
    float4* d = (float4*)(Wdst + (size_t)row * G4);
#pragma unroll
    for (int it = 0; it < 4; ++it) {
        float4 v = s[threadIdx.x + it * 256];
        v.x = __uint_as_float(f2tf32(v.x));
        v.y = __uint_as_float(f2tf32(v.y));
        v.z = __uint_as_float(f2tf32(v.z));
        v.w = __uint_as_float(f2tf32(v.w));
        d[threadIdx.x + it * 256] = v;
    }
}

// ---------------- tf32 GEMM: C[M,N] = A[M,K] @ B[K,N] + bias[N] ----------------
#define GBM 128
#define GBN 128
#define GBK 16
#define LDA 20
#define LDB 136

__global__ void __launch_bounds__(256) gemm_tf32_kernel(
        const float* __restrict__ A, const float* __restrict__ B,
        const float* __restrict__ bias, float* __restrict__ C, int K, int N) {
    __shared__ float As[2][GBM * LDA];
    __shared__ float Bs[2][GBK * LDB];
    const int tid = threadIdx.x;
    const int lane = tid & 31, w = tid >> 5;
    const int wm = w >> 1, wn = w & 1;
    const int gi = lane >> 2, tg = lane & 3;
    const int bm = blockIdx.y, bn = blockIdx.x;

    const float* Ag = A + (size_t)bm * GBM * K;
    const float* Bg = B + (size_t)bn * GBN;

    const int ar  = tid >> 1;
    const int ac0 = (tid & 1) * 8;
    const int br  = tid >> 4;
    const int bc  = (tid & 15) * 4;

    float acc[2][8][4];
#pragma unroll
    for (int m = 0; m < 2; ++m)
#pragma unroll
        for (int n = 0; n < 8; ++n)
#pragma unroll
            for (int q = 0; q < 4; ++q) acc[m][n][q] = 0.f;

    auto stage = [&](int s, int kt) {
        const float* asrc = Ag + (size_t)ar * K + kt * GBK + ac0;
        float* adst = &As[s][ar * LDA + ac0];
        cp16(adst, asrc); cp16(adst + 4, asrc + 4);
        const float* bsrc = Bg + (size_t)(kt * GBK + br) * N + bc;
        float* bdst = &Bs[s][br * LDB + bc];
        cp16(bdst, bsrc); cp16(bdst + 64, bsrc + 64);
        cp_commit();
    };

    auto compute = [&](int s) {
#pragma unroll
        for (int ks = 0; ks < 2; ++ks) {
            unsigned af[2][4], bf[8][2];
#pragma unroll
            for (int m = 0; m < 2; ++m) {
                int rb = wm * 32 + m * 16;
                af[m][0] = f2tf32(As[s][(rb + gi) * LDA + ks * 8 + tg]);
                af[m][1] = f2tf32(As[s][(rb + gi + 8) * LDA + ks * 8 + tg]);
                af[m][2] = f2tf32(As[s][(rb + gi) * LDA + ks * 8 + tg + 4]);
                af[m][3] = f2tf32(As[s][(rb + gi + 8) * LDA + ks * 8 + tg + 4]);
            }
#pragma unroll
            for (int n = 0; n < 8; ++n) {
                int cb = wn * 64 + n * 8 + gi;
                bf[n][0] = f2tf32(Bs[s][(ks * 8 + tg) * LDB + cb]);
                bf[n][1] = f2tf32(Bs[s][(ks * 8 + tg + 4) * LDB + cb]);
            }
#pragma unroll
            for (int m = 0; m < 2; ++m)
#pragma unroll
                for (int n = 0; n < 8; ++n)
                    mma_tf32(acc[m][n], af[m], bf[n]);
        }
    };

    const int KT = K >> 4;
    stage(0, 0);
    for (int kt = 0; kt < KT; ++kt) {
        cp_wait0();
        __syncthreads();
        if (kt + 1 < KT) stage((kt + 1) & 1, kt + 1);
        compute(kt & 1);
    }

#pragma unroll
    for (int m = 0; m < 2; ++m) {
        int row = bm * GBM + wm * 32 + m * 16 + gi;
#pragma unroll
        for (int n = 0; n < 8; ++n) {
            int col = bn * GBN + wn * 64 + n * 8 + 2 * tg;
            float bi0 = bias[col], bi1 = bias[col + 1];
            float2 v0 = make_float2(acc[m][n][0] + bi0, acc[m][n][1] + bi1);
            float2 v1 = make_float2(acc[m][n][2] + bi0, acc[m][n][3] + bi1);
            *(float2*)(C + (size_t)row * N + col) = v0;
            *(float2*)(C + (size_t)(row + 8) * N + col) = v1;
        }
    }
}

// ---------------- one LSTM timestep v3 (warps split K; 2 LDS per mma) ----------------
// Grid: 128 blocks x 256 threads. Block b owns hidden units [b*8, b*8+8)
// (gate cols q*1024 + b*8 + j, 32 cols). Warp w owns k8-steps {2w, 2w+1} of each
// 128-wide K chunk and accumulates the FULL 32x32 tile; 8-way cross-warp K-sum
// via smem at the end. W comes pre-tf32-rounded (g_Wr), h pre-rounded at write,
// so the hot loop has zero cvt.
#define SK_STAGES 4
#define SKW_LD 40                      // (8*tg+gi) -> 32 distinct banks
#define SKH_LD 132                     // (4*gi+tg) -> 32 distinct banks
#define SKW_SZ (128 * SKW_LD)          // 5120 floats
#define SKH_SZ (32 * SKH_LD)           // 4224 floats
#define SK_STAGE_SZ (SKW_SZ + SKH_SZ)  // 9344 floats
#define SKG_LD 36
#define SKG_WSZ (32 * SKG_LD)          // 1152 floats; Gs = 8*1152 overlays stage 0
#define STEP_SMEM (SK_STAGES * SK_STAGE_SZ * 4)

__global__ void __launch_bounds__(256) step_kernel(
        const float* __restrict__ G, const float* __restrict__ Wr,
        float* __restrict__ H, float* __restrict__ C, int t) {
    extern __shared__ float sm[];
    float* Gs = sm;                    // overlay; only touched after all chunks done

    const int tid = threadIdx.x, b = blockIdx.x;
    const int lane = tid & 31, w = tid >> 5;
    const int gi = lane >> 2, tg = lane & 3;

    if (t > 0) {
        const float* hp = H + (size_t)(t - 1) * BATCH * HID;
        // staging maps
        const int wrow  = tid >> 1;             // 0..127 : k-row within chunk
        const int wbase = (tid & 1) * 16;       // 16-col half
        const int g0    = (tid & 1) * 2;        // gate-group pair
        const int hm    = tid >> 3;             // 0..31  : batch row
        const int hseg  = (tid & 7) * 16;       // 16-float segment

        auto stageS = [&](int s, int kc) {
            float* Wst = sm + s * SK_STAGE_SZ;
            float* Hst = Wst + SKW_SZ;
            const float* wsrc = Wr + (size_t)(kc * 128 + wrow) * G4 + b * 8;
            float* wdst = Wst + wrow * SKW_LD + wbase;
            cp16(wdst,      wsrc + g0 * 1024);
            cp16(wdst + 4,  wsrc + g0 * 1024 + 4);
            cp16(wdst + 8,  wsrc + (g0 + 1) * 1024);
            cp16(wdst + 12, wsrc + (g0 + 1) * 1024 + 4);
            const float* hsrc = hp + (size_t)hm * HID + kc * 128 + hseg;
            float* hdst = Hst + hm * SKH_LD + hseg;
            cp16(hdst, hsrc);           cp16(hdst + 4, hsrc + 4);
            cp16(hdst + 8, hsrc + 8);   cp16(hdst + 12, hsrc + 12);
            cp_commit();
        };

        float acc[2][4][4];
#pragma unroll
        for (int m = 0; m < 2; ++m)
#pragma unroll
            for (int n = 0; n < 4; ++n)
#pragma unroll
                for (int q = 0; q < 4; ++q) acc[m][n][q] = 0.f;

        stageS(0, 0); stageS(1, 1); stageS(2, 2);
        for (int kc = 0; kc < 8; ++kc) {
            if (kc <= 5)      cp_wait2();
            else if (kc == 6) cp_wait1();
            else              cp_wait0();
            __syncthreads();
            if (kc + 3 < 8) stageS((kc + 3) & 3, kc + 3);
            const float* Wst = sm + (kc & 3) * SK_STAGE_SZ;
            const float* Hst = Wst + SKW_SZ;
#pragma unroll
            for (int s2 = 0; s2 < 2; ++s2) {
                const int k0 = (2 * w + s2) * 8;    // this warp's k8-slice
                unsigned a[2][4], bf[4][2];
#pragma unroll
                for (int m = 0; m < 2; ++m) {
                    const float* hr = Hst + (m * 16 + gi) * SKH_LD + k0;
                    a[m][0] = __float_as_uint(hr[tg]);
                    a[m][1] = __float_as_uint(hr[8 * SKH_LD + tg]);
                    a[m][2] = __float_as_uint(hr[tg + 4]);
                    a[m][3] = __float_as_uint(hr[8 * SKH_LD + tg + 4]);
                }
#pragma unroll
                for (int n = 0; n < 4; ++n) {
                    bf[n][0] = __float_as_uint(Wst[(k0 + tg) * SKW_LD + n * 8 + gi]);
                    bf[n][1] = __float_as_uint(Wst[(k0 + tg + 4) * SKW_LD + n * 8 + gi]);
                }
#pragma unroll
                for (int m = 0; m < 2; ++m)
#pragma unroll
                    for (int n = 0; n < 4; ++n)
                        mma_tf32(acc[m][n], a[m], bf[n]);
            }
            __syncthreads();
        }
        // cross-warp K reduction: each warp dumps its 32x32 partial to Gs[w]
        __syncthreads();   // stage buffers dead; Gs overlay now safe
        {
            float* gw = Gs + w * SKG_WSZ;
#pragma unroll
            for (int m = 0; m < 2; ++m)
#pragma unroll
                for (int n = 0; n < 4; ++n) {
                    int r0 = (m * 16 + gi) * SKG_LD + n * 8 + 2 * tg;
                    *(float2*)(gw + r0)               = make_float2(acc[m][n][0], acc[m][n][1]);
                    *(float2*)(gw + r0 + 8 * SKG_LD)  = make_float2(acc[m][n][2], acc[m][n][3]);
                }
        }
    }
    __syncthreads();

    // elementwise LSTM: one (batch, unit) per thread; h stored tf32-rounded
    {
        const int eb = tid >> 3;
        const int j  = tid & 7;
        const size_t go = ((size_t)t * BATCH + eb) * G4 + b * 8 + j;
        float iv = G[go];
        float gv = G[go + 1024];
        float fv = G[go + 2048];
        float ov = G[go + 3072];
        float cprev = 0.f;
        if (t > 0) {
#pragma unroll
            for (int w8 = 0; w8 < 8; ++w8) {
                const float* gw = Gs + w8 * SKG_WSZ + eb * SKG_LD;
                iv += gw[j];
                gv += gw[8 + j];
                fv += gw[16 + j];
                ov += gw[24 + j];
            }
            cprev = C[eb * HID + b * 8 + j];
        }
        float cn = sigmf(fv + 1.f) * cprev + sigmf(iv) * tanhf(gv);
        float hn = sigmf(ov) * tanhf(cn);
        C[eb * HID + b * 8 + j] = cn;
        H[((size_t)t * BATCH + eb) * HID + b * 8 + j] = __uint_as_float(f2tf32(hn));
    }
}

// ---------------- launch ----------------
extern "C" void kernel_launch(void* const* d_in, const int* in_sizes, int n_in,
                              void* d_out, int out_size) {
    (void)in_sizes; (void)n_in; (void)out_size;
    const void*  data = d_in[0];
    // d_in[1] = is_training (eval mode; unused)
    const float* emb  = (const float*)d_in[2];
    const float* W0   = (const float*)d_in[3];
    const float* b0   = (const float*)d_in[4];
    const float* W1   = (const float*)d_in[5];
    const float* b1   = (const float*)d_in[6];
    const float* W2   = (const float*)d_in[7];
    const float* b2   = (const float*)d_in[8];
    const float* Wd   = (const float*)d_in[9];
    const float* bd   = (const float*)d_in[10];
    float* out = (float*)d_out;

    void *pX0, *pG, *pHa, *pHb, *pC, *pWr;
    cudaGetSymbolAddress(&pX0, g_X0);
    cudaGetSymbolAddress(&pG,  g_G);
    cudaGetSymbolAddress(&pHa, g_Ha);
    cudaGetSymbolAddress(&pHb, g_Hb);
    cudaGetSymbolAddress(&pC,  g_C);
    cudaGetSymbolAddress(&pWr, g_Wr);
    float* X0 = (float*)pX0;
    float* G  = (float*)pG;
    float* Ha = (float*)pHa;
    float* Hb = (float*)pHb;
    float* C  = (float*)pC;
    float* Wr = (float*)pWr;

    cudaFuncSetAttribute(step_kernel, cudaFuncAttributeMaxDynamicSharedMemorySize, STEP_SMEM);

    embed_kernel<<<MROWS, 128>>>(data, emb, X0);

    // pre-round recurrent weight blocks (rows Din..Din+1023) once per layer
    preround_kernel<<<HID, 256>>>(W0 + (size_t)EMB * G4, Wr);
    preround_kernel<<<HID, 256>>>(W1 + (size_t)HID * G4, Wr + (size_t)HID * G4);
    preround_kernel<<<HID, 256>>>(W2 + (size_t)HID * G4, Wr + 2 * (size_t)HID * G4);

    // layer 0
    gemm_tf32_kernel<<<dim3(G4 / GBN, MROWS / GBM), 256>>>(X0, W0, b0, G, EMB, G4);
    for (int t = 0; t < T_LEN; ++t)
        step_kernel<<<128, 256, STEP_SMEM>>>(G, Wr, Ha, C, t);
    // layer 1
    gemm_tf32_kernel<<<dim3(G4 / GBN, MROWS / GBM), 256>>>(Ha, W1, b1, G, HID, G4);
    for (int t = 0; t < T_LEN; ++t)
        step_kernel<<<128, 256, STEP_SMEM>>>(G, Wr + (size_t)HID * G4, Hb, C, t);
    // layer 2
    gemm_tf32_kernel<<<dim3(G4 / GBN, MROWS / GBM), 256>>>(Hb, W2, b2, G, HID, G4);
    for (int t = 0; t < T_LEN; ++t)
        step_kernel<<<128, 256, STEP_SMEM>>>(G, Wr + 2 * (size_t)HID * G4, Ha, C, t);
    // decoder
    gemm_tf32_kernel<<<dim3(VOCAB / GBN, MROWS / GBM), 256>>>(Ha, Wd, bd, out, HID, VOCAB);
}

// round 11
// speedup vs baseline: 2.5656x; 1.2345x over previous
#include <cuda_runtime.h>
#include <cstddef>
#include <cstdint>

#define T_LEN 256
#define BATCH 32
#define VOCAB 32000
#define EMB 512
#define HID 1024
#define G4 4096
#define MROWS 8192  // T*B

// ---------------- scratch (no cudaMalloc allowed) ----------------
__device__ float g_X0[MROWS * EMB];
__device__ float g_G [MROWS * G4];
__device__ float g_Ha[MROWS * HID];
__device__ float g_Hb[MROWS * HID];
__device__ unsigned g_bar_count = 0;
__device__ volatile unsigned g_bar_gen = 0;

// ---------------- helpers ----------------
__device__ __forceinline__ unsigned f2tf32(float x) {
    unsigned r;
    asm("cvt.rna.tf32.f32 %0, %1;" : "=r"(r) : "f"(x));
    return r;
}

__device__ __forceinline__ void mma_tf32(float* d, const unsigned* a, const unsigned* b) {
    asm volatile(
        "mma.sync.aligned.m16n8k8.row.col.f32.tf32.tf32.f32 "
        "{%0,%1,%2,%3}, {%4,%5,%6,%7}, {%8,%9}, {%0,%1,%2,%3};\n"
        : "+f"(d[0]), "+f"(d[1]), "+f"(d[2]), "+f"(d[3])
        : "r"(a[0]), "r"(a[1]), "r"(a[2]), "r"(a[3]), "r"(b[0]), "r"(b[1]));
}

__device__ __forceinline__ void cp16(void* smem_dst, const void* gsrc) {
    unsigned d = (unsigned)__cvta_generic_to_shared(smem_dst);
    asm volatile("cp.async.cg.shared.global [%0], [%1], 16;\n" :: "r"(d), "l"(gsrc));
}
__device__ __forceinline__ void cp_commit() { asm volatile("cp.async.commit_group;\n" ::); }
__device__ __forceinline__ void cp_wait0()  { asm volatile("cp.async.wait_group 0;\n" ::: "memory"); }
__device__ __forceinline__ void cp_wait1()  { asm volatile("cp.async.wait_group 1;\n" ::: "memory"); }
__device__ __forceinline__ void cp_wait2()  { asm volatile("cp.async.wait_group 2;\n" ::: "memory"); }

__device__ __forceinline__ float sigmf(float x) { return 1.f / (1.f + expf(-x)); }

// sense-reversing grid barrier; safe: grid=128 <= 148 SMs -> single-wave residency
__device__ __forceinline__ void gsync() {
    __syncthreads();
    if (threadIdx.x == 0) {
        __threadfence();
        unsigned gen = g_bar_gen;
        if (atomicAdd(&g_bar_count, 1) == 127) {
            g_bar_count = 0;
            __threadfence();
            g_bar_gen = gen + 1;
        } else {
            while (g_bar_gen == gen) __nanosleep(32);
            __threadfence();
        }
    }
    __syncthreads();
}

// ---------------- embedding gather (int32/int64 token auto-detect) ----------------
__global__ void embed_kernel(const void* __restrict__ data, const float* __restrict__ emb,
                             float* __restrict__ X) {
    const int r = blockIdx.x;
    const unsigned* d32 = (const unsigned*)data;
    unsigned hi = 0;
#pragma unroll
    for (int k = 0; k < 16; ++k) hi |= d32[2 * k + 1];
    long long idx;
    if (hi == 0) idx = ((const long long*)data)[r];
    else         idx = (long long)((const int*)data)[r];
    const float4* s = (const float4*)(emb + (size_t)idx * EMB);
    float4* dst = (float4*)(X + (size_t)r * EMB);
    dst[threadIdx.x] = s[threadIdx.x];
}

// ---------------- tf32 GEMM: C[M,N] = A[M,K] @ B[K,N] + bias[N] ----------------
#define GBM 128
#define GBN 128
#define GBK 16
#define LDA 20
#define LDB 136

__global__ void __launch_bounds__(256) gemm_tf32_kernel(
        const float* __restrict__ A, const float* __restrict__ B,
        const float* __restrict__ bias, float* __restrict__ C, int K, int N) {
    __shared__ float As[2][GBM * LDA];
    __shared__ float Bs[2][GBK * LDB];
    const int tid = threadIdx.x;
    const int lane = tid & 31, w = tid >> 5;
    const int wm = w >> 1, wn = w & 1;
    const int gi = lane >> 2, tg = lane & 3;
    const int bm = blockIdx.y, bn = blockIdx.x;

    const float* Ag = A + (size_t)bm * GBM * K;
    const float* Bg = B + (size_t)bn * GBN;

    const int ar  = tid >> 1;
    const int ac0 = (tid & 1) * 8;
    const int br  = tid >> 4;
    const int bc  = (tid & 15) * 4;

    float acc[2][8][4];
#pragma unroll
    for (int m = 0; m < 2; ++m)
#pragma unroll
        for (int n = 0; n < 8; ++n)
#pragma unroll
            for (int q = 0; q < 4; ++q) acc[m][n][q] = 0.f;

    auto stage = [&](int s, int kt) {
        const float* asrc = Ag + (size_t)ar * K + kt * GBK + ac0;
        float* adst = &As[s][ar * LDA + ac0];
        cp16(adst, asrc); cp16(adst + 4, asrc + 4);
        const float* bsrc = Bg + (size_t)(kt * GBK + br) * N + bc;
        float* bdst = &Bs[s][br * LDB + bc];
        cp16(bdst, bsrc); cp16(bdst + 64, bsrc + 64);
        cp_commit();
    };

    auto compute = [&](int s) {
#pragma unroll
        for (int ks = 0; ks < 2; ++ks) {
            unsigned af[2][4], bf[8][2];
#pragma unroll
            for (int m = 0; m < 2; ++m) {
                int rb = wm * 32 + m * 16;
                af[m][0] = f2tf32(As[s][(rb + gi) * LDA + ks * 8 + tg]);
                af[m][1] = f2tf32(As[s][(rb + gi + 8) * LDA + ks * 8 + tg]);
                af[m][2] = f2tf32(As[s][(rb + gi) * LDA + ks * 8 + tg + 4]);
                af[m][3] = f2tf32(As[s][(rb + gi + 8) * LDA + ks * 8 + tg + 4]);
            }
#pragma unroll
            for (int n = 0; n < 8; ++n) {
                int cb = wn * 64 + n * 8 + gi;
                bf[n][0] = f2tf32(Bs[s][(ks * 8 + tg) * LDB + cb]);
                bf[n][1] = f2tf32(Bs[s][(ks * 8 + tg + 4) * LDB + cb]);
            }
#pragma unroll
            for (int m = 0; m < 2; ++m)
#pragma unroll
                for (int n = 0; n < 8; ++n)
                    mma_tf32(acc[m][n], af[m], bf[n]);
        }
    };

    const int KT = K >> 4;
    stage(0, 0);
    for (int kt = 0; kt < KT; ++kt) {
        cp_wait0();
        __syncthreads();
        if (kt + 1 < KT) stage((kt + 1) & 1, kt + 1);
        compute(kt & 1);
    }

#pragma unroll
    for (int m = 0; m < 2; ++m) {
        int row = bm * GBM + wm * 32 + m * 16 + gi;
#pragma unroll
        for (int n = 0; n < 8; ++n) {
            int col = bn * GBN + wn * 64 + n * 8 + 2 * tg;
            float bi0 = bias[col], bi1 = bias[col + 1];
            float2 v0 = make_float2(acc[m][n][0] + bi0, acc[m][n][1] + bi1);
            float2 v1 = make_float2(acc[m][n][2] + bi0, acc[m][n][3] + bi1);
            *(float2*)(C + (size_t)row * N + col) = v0;
            *(float2*)(C + (size_t)(row + 8) * N + col) = v1;
        }
    }
}

// ---------------- persistent LSTM recurrence (one kernel per layer) ----------------
// Grid: 128 blocks x 256 threads, single wave. Block b owns hidden units
// [b*8, b*8+8) -> gate cols q*1024 + b*8 + j (32 cols). Wh slice (1024x32,
// tf32-rounded) loaded into SMEM ONCE; 256 timesteps with per-step grid barrier.
// Per step: stage h_{t-1} chunks (4-stage cp.async), warps split K (warp w owns
// k8-slices 2w,2w+1 of each 128-chunk), cross-warp K-reduce in smem overlay,
// elementwise LSTM with c in registers, h written tf32-rounded.
#define RW_LD 36                        // 2-way LDS conflicts max on B-frags
#define RWSM (1024 * RW_LD)             // 36864 floats = 147.5 KB
#define RH_LD 132                       // (4*gi+tg) -> distinct banks
#define RH_SZ (32 * RH_LD)              // 4224 floats
#define RH_STAGES 4
#define RGS_LD 36
#define RGS_WSZ (32 * RGS_LD)           // 1152 floats/warp; 8 warps overlay h stages
#define RECUR_SMEM ((RWSM + RH_STAGES * RH_SZ) * 4)   // 215040 B

__global__ void __launch_bounds__(256) recur_kernel(
        const float* __restrict__ G, const float* __restrict__ W, int Din,
        float* __restrict__ H) {
    extern __shared__ float sm[];
    float* Wsm = sm;                    // [1024][36], persistent
    float* Hsm = sm + RWSM;             // 4 x [32][132]
    float* Gs  = Hsm;                   // overlay, used after all chunks computed

    const int tid = threadIdx.x, b = blockIdx.x;
    const int lane = tid & 31, w = tid >> 5;
    const int gi = lane >> 2, tg = lane & 3;

    // ---- load Wh slice once (tf32-rounded) ----
#pragma unroll
    for (int i = 0; i < 32; ++i) {
        int idx  = i * 256 + tid;       // 0..8191
        int row  = idx >> 3;            // 0..1023
        int q    = (idx >> 1) & 3;      // gate group
        int half = (idx & 1) * 4;
        float4 v = *(const float4*)(W + (size_t)(Din + row) * G4 + q * 1024 + b * 8 + half);
        v.x = __uint_as_float(f2tf32(v.x));
        v.y = __uint_as_float(f2tf32(v.y));
        v.z = __uint_as_float(f2tf32(v.z));
        v.w = __uint_as_float(f2tf32(v.w));
        *(float4*)(Wsm + row * RW_LD + q * 8 + half) = v;
    }
    __syncthreads();

    const int eb = tid >> 3, j = tid & 7;        // elementwise: (batch, unit)
    const int hm = tid >> 3, hseg = (tid & 7) * 16;  // h staging map
    float creg = 0.f;                             // cell state in register

    for (int t = 0; t < T_LEN; ++t) {
        // prefetch G[t] gate values (hidden under the mma work)
        const size_t go = ((size_t)t * BATCH + eb) * G4 + b * 8 + j;
        float giv = G[go];
        float ggv = G[go + 1024];
        float gfv = G[go + 2048];
        float gov = G[go + 3072];

        if (t > 0) {
            const float* hp = H + (size_t)(t - 1) * BATCH * HID;
            auto stageH = [&](int s, int kc) {
                const float* hsrc = hp + (size_t)hm * HID + kc * 128 + hseg;
                float* hdst = Hsm + s * RH_SZ + hm * RH_LD + hseg;
                cp16(hdst, hsrc);           cp16(hdst + 4, hsrc + 4);
                cp16(hdst + 8, hsrc + 8);   cp16(hdst + 12, hsrc + 12);
                cp_commit();
            };

            float acc[2][4][4];
#pragma unroll
            for (int m = 0; m < 2; ++m)
#pragma unroll
                for (int n = 0; n < 4; ++n)
#pragma unroll
                    for (int q = 0; q < 4; ++q) acc[m][n][q] = 0.f;

            stageH(0, 0); stageH(1, 1); stageH(2, 2);
#pragma unroll
            for (int kc = 0; kc < 8; ++kc) {
                if (kc <= 5)      cp_wait2();
                else if (kc == 6) cp_wait1();
                else              cp_wait0();
                __syncthreads();
                if (kc + 3 < 8) stageH((kc + 3) & 3, kc + 3);
                const float* Hst = Hsm + (kc & 3) * RH_SZ;
                const float* Wst = Wsm + kc * 128 * RW_LD;
#pragma unroll
                for (int s2 = 0; s2 < 2; ++s2) {
                    const int k0 = (2 * w + s2) * 8;   // this warp's k8-slice
                    unsigned a[2][4], bf[4][2];
#pragma unroll
                    for (int m = 0; m < 2; ++m) {
                        const float* hr = Hst + (m * 16 + gi) * RH_LD + k0;
                        a[m][0] = __float_as_uint(hr[tg]);
                        a[m][1] = __float_as_uint(hr[8 * RH_LD + tg]);
                        a[m][2] = __float_as_uint(hr[tg + 4]);
                        a[m][3] = __float_as_uint(hr[8 * RH_LD + tg + 4]);
                    }
#pragma unroll
                    for (int n = 0; n < 4; ++n) {
                        bf[n][0] = __float_as_uint(Wst[(k0 + tg) * RW_LD + n * 8 + gi]);
                        bf[n][1] = __float_as_uint(Wst[(k0 + tg + 4) * RW_LD + n * 8 + gi]);
                    }
#pragma unroll
                    for (int m = 0; m < 2; ++m)
#pragma unroll
                        for (int n = 0; n < 4; ++n)
                            mma_tf32(acc[m][n], a[m], bf[n]);
                }
                __syncthreads();
            }
            // cross-warp K reduction: dump 32x32 partials into overlay
            {
                float* gw = Gs + w * RGS_WSZ;
#pragma unroll
                for (int m = 0; m < 2; ++m)
#pragma unroll
                    for (int n = 0; n < 4; ++n) {
                        int r0 = (m * 16 + gi) * RGS_LD + n * 8 + 2 * tg;
                        *(float2*)(gw + r0)              = make_float2(acc[m][n][0], acc[m][n][1]);
                        *(float2*)(gw + r0 + 8 * RGS_LD) = make_float2(acc[m][n][2], acc[m][n][3]);
                    }
            }
        }
        __syncthreads();

        // elementwise LSTM
        {
            float iv = giv, gv = ggv, fv = gfv, ov = gov;
            if (t > 0) {
#pragma unroll
                for (int w8 = 0; w8 < 8; ++w8) {
                    const float* gw = Gs + w8 * RGS_WSZ + eb * RGS_LD;
                    iv += gw[j];
                    gv += gw[8 + j];
                    fv += gw[16 + j];
                    ov += gw[24 + j];
                }
            }
            creg = sigmf(fv + 1.f) * creg + sigmf(iv) * tanhf(gv);
            float hn = sigmf(ov) * tanhf(creg);
            H[((size_t)t * BATCH + eb) * HID + b * 8 + j] = __uint_as_float(f2tf32(hn));
        }
        if (t + 1 < T_LEN) gsync();   // orders H[t] writes before step t+1 reads
    }
}

// ---------------- launch ----------------
extern "C" void kernel_launch(void* const* d_in, const int* in_sizes, int n_in,
                              void* d_out, int out_size) {
    (void)in_sizes; (void)n_in; (void)out_size;
    const void*  data = d_in[0];
    // d_in[1] = is_training (eval mode; unused)
    const float* emb  = (const float*)d_in[2];
    const float* W0   = (const float*)d_in[3];
    const float* b0   = (const float*)d_in[4];
    const float* W1   = (const float*)d_in[5];
    const float* b1   = (const float*)d_in[6];
    const float* W2   = (const float*)d_in[7];
    const float* b2   = (const float*)d_in[8];
    const float* Wd   = (const float*)d_in[9];
    const float* bd   = (const float*)d_in[10];
    float* out = (float*)d_out;

    void *pX0, *pG, *pHa, *pHb;
    cudaGetSymbolAddress(&pX0, g_X0);
    cudaGetSymbolAddress(&pG,  g_G);
    cudaGetSymbolAddress(&pHa, g_Ha);
    cudaGetSymbolAddress(&pHb, g_Hb);
    float* X0 = (float*)pX0;
    float* G  = (float*)pG;
    float* Ha = (float*)pHa;
    float* Hb = (float*)pHb;

    cudaFuncSetAttribute(recur_kernel, cudaFuncAttributeMaxDynamicSharedMemorySize, RECUR_SMEM);

    embed_kernel<<<MROWS, 128>>>(data, emb, X0);

    // layer 0
    gemm_tf32_kernel<<<dim3(G4 / GBN, MROWS / GBM), 256>>>(X0, W0, b0, G, EMB, G4);
    recur_kernel<<<128, 256, RECUR_SMEM>>>(G, W0, EMB, Ha);
    // layer 1
    gemm_tf32_kernel<<<dim3(G4 / GBN, MROWS / GBM), 256>>>(Ha, W1, b1, G, HID, G4);
    recur_kernel<<<128, 256, RECUR_SMEM>>>(G, W1, HID, Hb);
    // layer 2
    gemm_tf32_kernel<<<dim3(G4 / GBN, MROWS / GBM), 256>>>(Hb, W2, b2, G, HID, G4);
    recur_kernel<<<128, 256, RECUR_SMEM>>>(G, W2, HID, Ha);
    // decoder
    gemm_tf32_kernel<<<dim3(VOCAB / GBN, MROWS / GBM), 256>>>(Ha, Wd, bd, out, HID, VOCAB);
}

// round 13
// speedup vs baseline: 2.6837x; 1.0460x over previous
#include <cuda_runtime.h>
#include <cstddef>
#include <cstdint>

#define T_LEN 256
#define BATCH 32
#define VOCAB 32000
#define EMB 512
#define HID 1024
#define G4 4096
#define MROWS 8192  // T*B

// ---------------- scratch (no cudaMalloc allowed) ----------------
__device__ float g_X0[MROWS * EMB];
__device__ float g_G [MROWS * G4];
__device__ float g_Ha[MROWS * HID];
__device__ float g_Hb[MROWS * HID];
__device__ float g_Wg [2560 * G4];      // tf32-rounded input-proj weights: W0[0:512], W1[0:1024], W2[0:1024]
__device__ float g_Wdr[HID * VOCAB];    // tf32-rounded decoder weights
__device__ unsigned g_bar_count = 0;
__device__ volatile unsigned g_bar_gen = 0;

// ---------------- helpers ----------------
__device__ __forceinline__ unsigned f2tf32(float x) {
    unsigned r;
    asm("cvt.rna.tf32.f32 %0, %1;" : "=r"(r) : "f"(x));
    return r;
}

__device__ __forceinline__ void mma_tf32(float* d, const unsigned* a, const unsigned* b) {
    asm volatile(
        "mma.sync.aligned.m16n8k8.row.col.f32.tf32.tf32.f32 "
        "{%0,%1,%2,%3}, {%4,%5,%6,%7}, {%8,%9}, {%0,%1,%2,%3};\n"
        : "+f"(d[0]), "+f"(d[1]), "+f"(d[2]), "+f"(d[3])
        : "r"(a[0]), "r"(a[1]), "r"(a[2]), "r"(a[3]), "r"(b[0]), "r"(b[1]));
}

__device__ __forceinline__ void cp16(void* smem_dst, const void* gsrc) {
    unsigned d = (unsigned)__cvta_generic_to_shared(smem_dst);
    asm volatile("cp.async.cg.shared.global [%0], [%1], 16;\n" :: "r"(d), "l"(gsrc));
}
__device__ __forceinline__ void cp_commit() { asm volatile("cp.async.commit_group;\n" ::); }
__device__ __forceinline__ void cp_wait0()  { asm volatile("cp.async.wait_group 0;\n" ::: "memory"); }
__device__ __forceinline__ void cp_wait1()  { asm volatile("cp.async.wait_group 1;\n" ::: "memory"); }
__device__ __forceinline__ void cp_wait2()  { asm volatile("cp.async.wait_group 2;\n" ::: "memory"); }

__device__ __forceinline__ float sigmf(float x) { return 1.f / (1.f + expf(-x)); }

// sense-reversing grid barrier; safe: grid=128 <= 148 SMs -> single-wave residency
__device__ __forceinline__ void gsync() {
    __syncthreads();
    if (threadIdx.x == 0) {
        __threadfence();
        unsigned gen = g_bar_gen;
        if (atomicAdd(&g_bar_count, 1) == 127) {
            g_bar_count = 0;
            __threadfence();
            g_bar_gen = gen + 1;
        } else {
            while (g_bar_gen == gen) __nanosleep(32);
            __threadfence();
        }
    }
    __syncthreads();
}

// ---------------- embedding gather (writes tf32-rounded) ----------------
__global__ void embed_kernel(const void* __restrict__ data, const float* __restrict__ emb,
                             float* __restrict__ X) {
    const int r = blockIdx.x;
    const unsigned* d32 = (const unsigned*)data;
    unsigned hi = 0;
#pragma unroll
    for (int k = 0; k < 16; ++k) hi |= d32[2 * k + 1];
    long long idx;
    if (hi == 0) idx = ((const long long*)data)[r];
    else         idx = (long long)((const int*)data)[r];
    float4 v = ((const float4*)(emb + (size_t)idx * EMB))[threadIdx.x];
    v.x = __uint_as_float(f2tf32(v.x));
    v.y = __uint_as_float(f2tf32(v.y));
    v.z = __uint_as_float(f2tf32(v.z));
    v.w = __uint_as_float(f2tf32(v.w));
    ((float4*)(X + (size_t)r * EMB))[threadIdx.x] = v;
}

// ---------------- pre-round weights to tf32 (one block per row) ----------------
__global__ void preround_kernel(const float* __restrict__ src, float* __restrict__ dst,
                                int width) {
    const size_t row = blockIdx.x;
    const float4* s = (const float4*)(src + row * width);
    float4* d = (float4*)(dst + row * width);
    const int n4 = width >> 2;
    for (int c = threadIdx.x; c < n4; c += 256) {
        float4 v = s[c];
        v.x = __uint_as_float(f2tf32(v.x));
        v.y = __uint_as_float(f2tf32(v.y));
        v.z = __uint_as_float(f2tf32(v.z));
        v.w = __uint_as_float(f2tf32(v.w));
        d[c] = v;
    }
}

// ---------------- tf32 GEMM: C = A @ B + bias; A,B pre-rounded to tf32 ----------------
// 4-stage cp.async pipeline, no cvt in the hot loop.
#define GBM 128
#define GBN 128
#define GBK 16
#define LDA 20
#define LDB 136
#define G_ASZ (GBM * LDA)
#define G_BSZ (GBK * LDB)
#define G_STG (G_ASZ + G_BSZ)
#define GEMM_SMEM (4 * G_STG * 4)

__global__ void __launch_bounds__(256) gemm_tf32_kernel(
        const float* __restrict__ A, const float* __restrict__ B,
        const float* __restrict__ bias, float* __restrict__ C, int K, int N) {
    extern __shared__ float sm[];
    const int tid = threadIdx.x;
    const int lane = tid & 31, w = tid >> 5;
    const int wm = w >> 1, wn = w & 1;      // 4x2 warp grid, warp tile 32x64
    const int gi = lane >> 2, tg = lane & 3;
    const int bm = blockIdx.y, bn = blockIdx.x;

    const float* Ag = A + (size_t)bm * GBM * K;
    const float* Bg = B + (size_t)bn * GBN;

    const int ar  = tid >> 1;
    const int ac0 = (tid & 1) * 8;
    const int br  = tid >> 4;
    const int bc  = (tid & 15) * 4;

    float acc[2][8][4];
#pragma unroll
    for (int m = 0; m < 2; ++m)
#pragma unroll
        for (int n = 0; n < 8; ++n)
#pragma unroll
            for (int q = 0; q < 4; ++q) acc[m][n][q] = 0.f;

    auto stage = [&](int s, int kt) {
        float* As = sm + s * G_STG;
        float* Bs = As + G_ASZ;
        const float* asrc = Ag + (size_t)ar * K + kt * GBK + ac0;
        float* adst = As + ar * LDA + ac0;
        cp16(adst, asrc); cp16(adst + 4, asrc + 4);
        const float* bsrc = Bg + (size_t)(kt * GBK + br) * N + bc;
        float* bdst = Bs + br * LDB + bc;
        cp16(bdst, bsrc); cp16(bdst + 64, bsrc + 64);
        cp_commit();
    };

    auto compute = [&](int s) {
        const float* As = sm + s * G_STG;
        const float* Bs = As + G_ASZ;
#pragma unroll
        for (int ks = 0; ks < 2; ++ks) {
            unsigned af[2][4], bf[8][2];
#pragma unroll
            for (int m = 0; m < 2; ++m) {
                int rb = wm * 32 + m * 16;
                af[m][0] = __float_as_uint(As[(rb + gi) * LDA + ks * 8 + tg]);
                af[m][1] = __float_as_uint(As[(rb + gi + 8) * LDA + ks * 8 + tg]);
                af[m][2] = __float_as_uint(As[(rb + gi) * LDA + ks * 8 + tg + 4]);
                af[m][3] = __float_as_uint(As[(rb + gi + 8) * LDA + ks * 8 + tg + 4]);
            }
#pragma unroll
            for (int n = 0; n < 8; ++n) {
                int cb = wn * 64 + n * 8 + gi;
                bf[n][0] = __float_as_uint(Bs[(ks * 8 + tg) * LDB + cb]);
                bf[n][1] = __float_as_uint(Bs[(ks * 8 + tg + 4) * LDB + cb]);
            }
#pragma unroll
            for (int m = 0; m < 2; ++m)
#pragma unroll
                for (int n = 0; n < 8; ++n)
                    mma_tf32(acc[m][n], af[m], bf[n]);
        }
    };

    const int KT = K >> 4;
    stage(0, 0); stage(1, 1); stage(2, 2);
    for (int kt = 0; kt < KT; ++kt) {
        if (kt <= KT - 3)      cp_wait2();
        else if (kt == KT - 2) cp_wait1();
        else                   cp_wait0();
        __syncthreads();
        if (kt + 3 < KT) stage((kt + 3) & 3, kt + 3);
        compute(kt & 3);
    }

#pragma unroll
    for (int m = 0; m < 2; ++m) {
        int row = bm * GBM + wm * 32 + m * 16 + gi;
#pragma unroll
        for (int n = 0; n < 8; ++n) {
            int col = bn * GBN + wn * 64 + n * 8 + 2 * tg;
            float bi0 = bias[col], bi1 = bias[col + 1];
            float2 v0 = make_float2(acc[m][n][0] + bi0, acc[m][n][1] + bi1);
            float2 v1 = make_float2(acc[m][n][2] + bi0, acc[m][n][3] + bi1);
            *(float2*)(C + (size_t)row * N + col) = v0;
            *(float2*)(C + (size_t)(row + 8) * N + col) = v1;
        }
    }
}

// ---------------- persistent LSTM recurrence (one kernel per layer) ----------------
#define RW_LD 36
#define RWSM (1024 * RW_LD)
#define RH_LD 132
#define RH_SZ (32 * RH_LD)
#define RH_STAGES 4
#define RGS_LD 36
#define RGS_WSZ (32 * RGS_LD)
#define RECUR_SMEM ((RWSM + RH_STAGES * RH_SZ) * 4)

__global__ void __launch_bounds__(256) recur_kernel(
        const float* __restrict__ G, const float* __restrict__ W, int Din,
        float* __restrict__ H) {
    extern __shared__ float sm[];
    float* Wsm = sm;
    float* Hsm = sm + RWSM;
    float* Gs  = Hsm;

    const int tid = threadIdx.x, b = blockIdx.x;
    const int lane = tid & 31, w = tid >> 5;
    const int gi = lane >> 2, tg = lane & 3;

    // load Wh slice once (tf32-rounded)
#pragma unroll
    for (int i = 0; i < 32; ++i) {
        int idx  = i * 256 + tid;
        int row  = idx >> 3;
        int q    = (idx >> 1) & 3;
        int half = (idx & 1) * 4;
        float4 v = *(const float4*)(W + (size_t)(Din + row) * G4 + q * 1024 + b * 8 + half);
        v.x = __uint_as_float(f2tf32(v.x));
        v.y = __uint_as_float(f2tf32(v.y));
        v.z = __uint_as_float(f2tf32(v.z));
        v.w = __uint_as_float(f2tf32(v.w));
        *(float4*)(Wsm + row * RW_LD + q * 8 + half) = v;
    }
    __syncthreads();

    const int eb = tid >> 3, j = tid & 7;
    const int hm = tid >> 3, hseg = (tid & 7) * 16;
    float creg = 0.f;

    for (int t = 0; t < T_LEN; ++t) {
        const size_t go = ((size_t)t * BATCH + eb) * G4 + b * 8 + j;
        float giv = G[go];
        float ggv = G[go + 1024];
        float gfv = G[go + 2048];
        float gov = G[go + 3072];

        if (t > 0) {
            const float* hp = H + (size_t)(t - 1) * BATCH * HID;
            auto stageH = [&](int s, int kc) {
                const float* hsrc = hp + (size_t)hm * HID + kc * 128 + hseg;
                float* hdst = Hsm + s * RH_SZ + hm * RH_LD + hseg;
                cp16(hdst, hsrc);           cp16(hdst + 4, hsrc + 4);
                cp16(hdst + 8, hsrc + 8);   cp16(hdst + 12, hsrc + 12);
                cp_commit();
            };

            float acc[2][4][4];
#pragma unroll
            for (int m = 0; m < 2; ++m)
#pragma unroll
                for (int n = 0; n < 4; ++n)
#pragma unroll
                    for (int q = 0; q < 4; ++q) acc[m][n][q] = 0.f;

            stageH(0, 0); stageH(1, 1); stageH(2, 2);
#pragma unroll
            for (int kc = 0; kc < 8; ++kc) {
                if (kc <= 5)      cp_wait2();
                else if (kc == 6) cp_wait1();
                else              cp_wait0();
                __syncthreads();
                if (kc + 3 < 8) stageH((kc + 3) & 3, kc + 3);
                const float* Hst = Hsm + (kc & 3) * RH_SZ;
                const float* Wst = Wsm + kc * 128 * RW_LD;
#pragma unroll
                for (int s2 = 0; s2 < 2; ++s2) {
                    const int k0 = (2 * w + s2) * 8;
                    unsigned a[2][4], bf[4][2];
#pragma unroll
                    for (int m = 0; m < 2; ++m) {
                        const float* hr = Hst + (m * 16 + gi) * RH_LD + k0;
                        a[m][0] = __float_as_uint(hr[tg]);
                        a[m][1] = __float_as_uint(hr[8 * RH_LD + tg]);
                        a[m][2] = __float_as_uint(hr[tg + 4]);
                        a[m][3] = __float_as_uint(hr[8 * RH_LD + tg + 4]);
                    }
#pragma unroll
                    for (int n = 0; n < 4; ++n) {
                        bf[n][0] = __float_as_uint(Wst[(k0 + tg) * RW_LD + n * 8 + gi]);
                        bf[n][1] = __float_as_uint(Wst[(k0 + tg + 4) * RW_LD + n * 8 + gi]);
                    }
#pragma unroll
                    for (int m = 0; m < 2; ++m)
#pragma unroll
                        for (int n = 0; n < 4; ++n)
                            mma_tf32(acc[m][n], a[m], bf[n]);
                }
                __syncthreads();
            }
            {
                float* gw = Gs + w * RGS_WSZ;
#pragma unroll
                for (int m = 0; m < 2; ++m)
#pragma unroll
                    for (int n = 0; n < 4; ++n) {
                        int r0 = (m * 16 + gi) * RGS_LD + n * 8 + 2 * tg;
                        *(float2*)(gw + r0)              = make_float2(acc[m][n][0], acc[m][n][1]);
                        *(float2*)(gw + r0 + 8 * RGS_LD) = make_float2(acc[m][n][2], acc[m][n][3]);
                    }
            }
        }
        __syncthreads();

        {
            float iv = giv, gv = ggv, fv = gfv, ov = gov;
            if (t > 0) {
#pragma unroll
                for (int w8 = 0; w8 < 8; ++w8) {
                    const float* gw = Gs + w8 * RGS_WSZ + eb * RGS_LD;
                    iv += gw[j];
                    gv += gw[8 + j];
                    fv += gw[16 + j];
                    ov += gw[24 + j];
                }
            }
            creg = sigmf(fv + 1.f) * creg + sigmf(iv) * tanhf(gv);
            float hn = sigmf(ov) * tanhf(creg);
            H[((size_t)t * BATCH + eb) * HID + b * 8 + j] = __uint_as_float(f2tf32(hn));
        }
        if (t + 1 < T_LEN) gsync();
    }
}

// ---------------- launch ----------------
extern "C" void kernel_launch(void* const* d_in, const int* in_sizes, int n_in,
                              void* d_out, int out_size) {
    (void)in_sizes; (void)n_in; (void)out_size;
    const void*  data = d_in[0];
    // d_in[1] = is_training (eval mode; unused)
    const float* emb  = (const float*)d_in[2];
    const float* W0   = (const float*)d_in[3];
    const float* b0   = (const float*)d_in[4];
    const float* W1   = (const float*)d_in[5];
    const float* b1   = (const float*)d_in[6];
    const float* W2   = (const float*)d_in[7];
    const float* b2   = (const float*)d_in[8];
    const float* Wd   = (const float*)d_in[9];
    const float* bd   = (const float*)d_in[10];
    float* out = (float*)d_out;

    void *pX0, *pG, *pHa, *pHb, *pWg, *pWdr;
    cudaGetSymbolAddress(&pX0,  g_X0);
    cudaGetSymbolAddress(&pG,   g_G);
    cudaGetSymbolAddress(&pHa,  g_Ha);
    cudaGetSymbolAddress(&pHb,  g_Hb);
    cudaGetSymbolAddress(&pWg,  g_Wg);
    cudaGetSymbolAddress(&pWdr, g_Wdr);
    float* X0  = (float*)pX0;
    float* G   = (float*)pG;
    float* Ha  = (float*)pHa;
    float* Hb  = (float*)pHb;
    float* Wg  = (float*)pWg;
    float* Wdr = (float*)pWdr;

    float* W0r = Wg;                         // 512 rows
    float* W1r = Wg + (size_t)512 * G4;      // 1024 rows
    float* W2r = Wg + (size_t)1536 * G4;     // 1024 rows

    cudaFuncSetAttribute(recur_kernel, cudaFuncAttributeMaxDynamicSharedMemorySize, RECUR_SMEM);
    cudaFuncSetAttribute(gemm_tf32_kernel, cudaFuncAttributeMaxDynamicSharedMemorySize, GEMM_SMEM);

    embed_kernel<<<MROWS, 128>>>(data, emb, X0);

    // pre-round GEMM weight operands (input-projection rows + decoder) to tf32
    preround_kernel<<<512,  256>>>(W0, W0r, G4);
    preround_kernel<<<1024, 256>>>(W1, W1r, G4);
    preround_kernel<<<1024, 256>>>(W2, W2r, G4);
    preround_kernel<<<1024, 256>>>(Wd, Wdr, VOCAB);

    // layer 0
    gemm_tf32_kernel<<<dim3(G4 / GBN, MROWS / GBM), 256, GEMM_SMEM>>>(X0, W0r, b0, G, EMB, G4);
    recur_kernel<<<128, 256, RECUR_SMEM>>>(G, W0, EMB, Ha);
    // layer 1
    gemm_tf32_kernel<<<dim3(G4 / GBN, MROWS / GBM), 256, GEMM_SMEM>>>(Ha, W1r, b1, G, HID, G4);
    recur_kernel<<<128, 256, RECUR_SMEM>>>(G, W1, HID, Hb);
    // layer 2
    gemm_tf32_kernel<<<dim3(G4 / GBN, MROWS / GBM), 256, GEMM_SMEM>>>(Hb, W2r, b2, G, HID, G4);
    recur_kernel<<<128, 256, RECUR_SMEM>>>(G, W2, HID, Ha);
    // decoder
    gemm_tf32_kernel<<<dim3(VOCAB / GBN, MROWS / GBM), 256, GEMM_SMEM>>>(Ha, Wdr, bd, out, HID, VOCAB);
}